// round 11
// baseline (speedup 1.0000x reference)
#include <cuda_runtime.h>
#include <cuda_fp16.h>
#include <cstdint>

#define CHANNELS 256
#define HW 4096
#define BATCH 2
#define F2COLS 5504            // padded pyramid cols per batch (uses 5440)
// level offsets: L0 0 (64x64), L1 4096 (32x32), L2 5120 (16x16), L3 5376 (8x8)
#define WSTRIDE 688            // per-pixel window: L0@0(289/290) L1@290(169/170) L2@460(121/122) L3@582(100/106)

__device__ __align__(16) __half g_f1h[BATCH * HW * CHANNELS];      // [b][m][k], scaled 1/16
__device__ __align__(16) __half g_f2h[BATCH * F2COLS * CHANNELS];  // [b][col][k]
__device__ __align__(16) __half g_W[(size_t)BATCH * HW * WSTRIDE]; // per-pixel windows (~11 MB)
__device__ int g_binstart[128];
__device__ int g_bincnt[128];
__device__ int g_blist[BATCH * HW];   // sorted pixel ids
__device__ int g_pos[BATCH * HW];     // pixel -> sorted position

// ===================== helpers ========================
__device__ __forceinline__ uint32_t smem_u32(const void* p) {
    uint32_t a;
    asm("{ .reg .u64 t; cvta.to.shared.u64 t, %1; cvt.u32.u64 %0, t; }" : "=r"(a) : "l"(p));
    return a;
}
__device__ __forceinline__ void cp_async16(uint32_t s, const void* g) {
    asm volatile("cp.async.cg.shared.global [%0], [%1], 16;" :: "r"(s), "l"(g));
}
__device__ __forceinline__ void cp_commit() { asm volatile("cp.async.commit_group;"); }
template <int N> __device__ __forceinline__ void cp_wait() {
    asm volatile("cp.async.wait_group %0;" :: "n"(N));
}
__device__ __forceinline__ void ldsm_x4(uint32_t* r, uint32_t addr) {
    asm volatile("ldmatrix.sync.aligned.m8n8.x4.shared.b16 {%0,%1,%2,%3}, [%4];"
                 : "=r"(r[0]), "=r"(r[1]), "=r"(r[2]), "=r"(r[3]) : "r"(addr));
}
__device__ __forceinline__ void ldsm_x2(uint32_t* r, uint32_t addr) {
    asm volatile("ldmatrix.sync.aligned.m8n8.x2.shared.b16 {%0,%1}, [%2];"
                 : "=r"(r[0]), "=r"(r[1]) : "r"(addr));
}
__device__ __forceinline__ void mma16816(float* c, const uint32_t* a, const uint32_t* b) {
    asm volatile("mma.sync.aligned.m16n8k16.row.col.f32.f16.f16.f32 "
                 "{%0,%1,%2,%3}, {%4,%5,%6,%7}, {%8,%9}, {%0,%1,%2,%3};"
                 : "+f"(c[0]), "+f"(c[1]), "+f"(c[2]), "+f"(c[3])
                 : "r"(a[0]), "r"(a[1]), "r"(a[2]), "r"(a[3]), "r"(b[0]), "r"(b[1]));
}

// ======================= f1: transpose + fp16 convert =======================
__global__ void cvt_f1(const float* __restrict__ src) {
    __shared__ float tile[32][33];
    const int b = blockIdx.z, p0 = blockIdx.x * 32, c0 = blockIdx.y * 32;
    const float* s = src + (size_t)b * CHANNELS * HW;
    #pragma unroll
    for (int r = threadIdx.y; r < 32; r += 8)
        tile[r][threadIdx.x] = s[(c0 + r) * HW + p0 + threadIdx.x] * 0.0625f; // 1/sqrt(256)
    __syncthreads();
    __half* d = g_f1h + (size_t)b * HW * CHANNELS;
    #pragma unroll
    for (int r = threadIdx.y; r < 32; r += 8)
        d[(p0 + r) * CHANNELS + c0 + threadIdx.x] = __float2half(tile[threadIdx.x][r]);
}

// ====== f2: fused transpose + fp16 convert + all 3 pool levels ==============
__global__ void __launch_bounds__(256) cvt_pool_f2(const float* __restrict__ src) {
    __shared__ float sfp[64][65];
    __shared__ float sL1[64][17];
    __shared__ float sL2[64][5];
    const int tid = threadIdx.x;
    const int tile = blockIdx.x, cg = blockIdx.y, b = blockIdx.z;
    const int ty = tile >> 3, tx = tile & 7;
    const int c0 = cg * 64;
    const float* s = src + ((size_t)b * CHANNELS + c0) * HW + (ty * 8) * 64 + tx * 8;

    #pragma unroll
    for (int rep = 0; rep < 2; rep++) {
        const int idx = tid + rep * 256;
        const int c = idx >> 3, iy = idx & 7;
        const float4* p = (const float4*)(s + c * HW + iy * 64);
        float4 v0 = p[0], v1 = p[1];
        sfp[c][iy * 8 + 0] = v0.x; sfp[c][iy * 8 + 1] = v0.y;
        sfp[c][iy * 8 + 2] = v0.z; sfp[c][iy * 8 + 3] = v0.w;
        sfp[c][iy * 8 + 4] = v1.x; sfp[c][iy * 8 + 5] = v1.y;
        sfp[c][iy * 8 + 6] = v1.z; sfp[c][iy * 8 + 7] = v1.w;
    }
    __syncthreads();

    __half* f2 = g_f2h + (size_t)b * F2COLS * CHANNELS;

    {   // L0 transpose write
        const int c2 = (tid & 31) * 2;
        #pragma unroll
        for (int pass = 0; pass < 8; pass++) {
            const int pl = (tid >> 5) + pass * 8;
            const int py = ty * 8 + (pl >> 3), px = tx * 8 + (pl & 7);
            *(__half2*)(f2 + (size_t)(py * 64 + px) * CHANNELS + c0 + c2) =
                __floats2half2_rn(sfp[c2][pl], sfp[c2 + 1][pl]);
        }
    }

    #pragma unroll
    for (int rep = 0; rep < 2; rep++) {    // L1: 16 cells
        const int idx = tid + rep * 256;
        const int c = (idx & 31) * 2, cell = idx >> 5;
        const int jy = cell >> 2, jx = cell & 3;
        const int p00 = (2 * jy) * 8 + 2 * jx;
        const float a0 = 0.25f * (sfp[c][p00] + sfp[c][p00 + 1] + sfp[c][p00 + 8] + sfp[c][p00 + 9]);
        const float a1 = 0.25f * (sfp[c + 1][p00] + sfp[c + 1][p00 + 1] + sfp[c + 1][p00 + 8] + sfp[c + 1][p00 + 9]);
        sL1[c][cell] = a0; sL1[c + 1][cell] = a1;
        const int col = 4096 + (ty * 4 + jy) * 32 + tx * 4 + jx;
        *(__half2*)(f2 + (size_t)col * CHANNELS + c0 + c) = __floats2half2_rn(a0, a1);
    }
    __syncthreads();

    if (tid < 128) {                        // L2: 4 cells
        const int c = (tid & 31) * 2, cell = tid >> 5;
        const int Jy = cell >> 1, Jx = cell & 1;
        const int q = (2 * Jy) * 4 + 2 * Jx;
        const float a0 = 0.25f * (sL1[c][q] + sL1[c][q + 1] + sL1[c][q + 4] + sL1[c][q + 5]);
        const float a1 = 0.25f * (sL1[c + 1][q] + sL1[c + 1][q + 1] + sL1[c + 1][q + 4] + sL1[c + 1][q + 5]);
        sL2[c][cell] = a0; sL2[c + 1][cell] = a1;
        const int col = 5120 + (ty * 2 + Jy) * 16 + tx * 2 + Jx;
        *(__half2*)(f2 + (size_t)col * CHANNELS + c0 + c) = __floats2half2_rn(a0, a1);
    }
    __syncthreads();

    if (tid < 32) {                         // L3: 1 cell
        const int c = tid * 2;
        const float a0 = 0.25f * (sL2[c][0] + sL2[c][1] + sL2[c][2] + sL2[c][3]);
        const float a1 = 0.25f * (sL2[c + 1][0] + sL2[c + 1][1] + sL2[c + 1][2] + sL2[c + 1][3]);
        const int col = 5376 + ty * 8 + tx;
        *(__half2*)(f2 + (size_t)col * CHANNELS + c0 + c) = __floats2half2_rn(a0, a1);
    }
}

// ============================ binning =======================================
__global__ void __launch_bounds__(1024) bin_pixels(const float* __restrict__ cc) {
    __shared__ int scnt[128], sstart[128];
    const int tid = threadIdx.x;
    if (tid < 128) scnt[tid] = 0;
    __syncthreads();
    int mycell[8];
    #pragma unroll
    for (int i = 0; i < 8; i++) {
        const int p = tid + i * 1024;
        const int b = p >> 12, pix = p & 4095;
        const float cx = cc[(b * 2 + 0) * HW + pix];
        const float cy = cc[(b * 2 + 1) * HW + pix];
        const int CX = min(7, max(0, ((int)floorf(cx)) >> 3));
        const int CY = min(7, max(0, ((int)floorf(cy)) >> 3));
        mycell[i] = b * 64 + CY * 8 + CX;
        atomicAdd(&scnt[mycell[i]], 1);
    }
    __syncthreads();
    if (tid < 32) {     // warp-parallel exclusive scan, 4 bins/lane
        const int c0 = scnt[tid * 4], c1 = scnt[tid * 4 + 1];
        const int c2 = scnt[tid * 4 + 2], c3 = scnt[tid * 4 + 3];
        const int sum = c0 + c1 + c2 + c3;
        int pre = sum;
        #pragma unroll
        for (int d = 1; d < 32; d <<= 1) {
            const int t = __shfl_up_sync(0xffffffffu, pre, d);
            if (tid >= d) pre += t;
        }
        const int excl = pre - sum;
        sstart[tid * 4] = excl;
        sstart[tid * 4 + 1] = excl + c0;
        sstart[tid * 4 + 2] = excl + c0 + c1;
        sstart[tid * 4 + 3] = excl + c0 + c1 + c2;
        g_binstart[tid * 4] = excl;
        g_binstart[tid * 4 + 1] = excl + c0;
        g_binstart[tid * 4 + 2] = excl + c0 + c1;
        g_binstart[tid * 4 + 3] = excl + c0 + c1 + c2;
        g_bincnt[tid * 4] = c0; g_bincnt[tid * 4 + 1] = c1;
        g_bincnt[tid * 4 + 2] = c2; g_bincnt[tid * 4 + 3] = c3;
    }
    __syncthreads();
    if (tid < 128) scnt[tid] = 0;   // reuse as cursor
    __syncthreads();
    #pragma unroll
    for (int i = 0; i < 8; i++) {
        const int p = tid + i * 1024;
        const int pos = sstart[mycell[i]] + atomicAdd(&scnt[mycell[i]], 1);
        g_blist[pos] = p;
        g_pos[p] = pos;
    }
}

// =================== fused all-level binned GEMM ============================
// One CTA per bin. A (rows x 256) resident in smem, loaded ONCE.
// 6 n-chunks x 128 combined window cols (= g_W layout), 3-stage B pipeline.
#define SRB 80
#define ASEC 10240            // one k-section of A: 128 rows x 80 B
#define BSTG 10240            // one B stage: 128 cols x 80 B
#define GEMM_SMEM (8 * ASEC + 3 * BSTG)   // 112640
#define NCHUNK 6

__global__ void __launch_bounds__(512) fused_gemm() {
    extern __shared__ __align__(16) char smem[];
    __shared__ int s_colidx[NCHUNK * 128];
    __shared__ int s_plist[128];

    const int bin = blockIdx.x;
    const int start = g_binstart[bin];
    int rows = g_bincnt[bin];
    if (rows > 128) rows = 128;
    if (rows <= 0) return;
    const int rows_pad = (rows + 31) & ~31;

    const int tid = threadIdx.x, wid = tid >> 5, lane = tid & 31;
    const int wmq = wid & 3, wn = wid >> 2;       // 4 m-quarters x 4 n-warps
    const int b = bin >> 6, cell = bin & 63;
    const int CY = cell >> 3, CX = cell & 7;
    const bool mactive = (wmq * 32) < rows;

    // combined column list == g_W layout
    for (int n = tid; n < NCHUNK * 128; n += 512) {
        int base, WW, SIZE, CW, off;
        if (n < 290)      { base = 0;   WW = 17; SIZE = 64; CW = 8; off = 0; }
        else if (n < 460) { base = 290; WW = 13; SIZE = 32; CW = 4; off = 4096; }
        else if (n < 582) { base = 460; WW = 11; SIZE = 16; CW = 2; off = 5120; }
        else              { base = 582; WW = 10; SIZE = 8;  CW = 1; off = 5376; }
        const int local = n - base;
        const int NL = WW * WW;
        int col = off;  // default for pad entries (safe gather)
        if (n < WSTRIDE && local < NL) {
            const int wy = local / WW, wx = local - wy * WW;
            const int iy = min(SIZE - 1, max(0, CW * CY - 4 + wy));
            const int ix = min(SIZE - 1, max(0, CW * CX - 4 + wx));
            col = off + iy * SIZE + ix;
        }
        s_colidx[n] = col * CHANNELS;
    }
    if (tid < 128)
        s_plist[tid] = g_blist[tid < rows ? (start + tid) : start];
    __syncthreads();

    const uint32_t Abase = smem_u32(smem);
    const uint32_t Bbase = Abase + 8 * ASEC;
    const __half* f2b = g_f2h + (size_t)b * F2COLS * CHANNELS;

    // stage A: 8 k-sections, one commit group (skipped quarters stay garbage)
    {
        const int r = tid >> 2, c = tid & 3;
        if (r < rows_pad) {
            const __half* a = g_f1h + (size_t)s_plist[r] * CHANNELS + c * 8;
            #pragma unroll
            for (int sec = 0; sec < 8; sec++)
                cp_async16(Abase + sec * ASEC + r * SRB + c * 16, a + sec * 32);
        }
        cp_commit();
    }

    auto issueB = [&](int ch, int kt, int stage) {
        const int n = tid >> 2, c = tid & 3;
        cp_async16(Bbase + stage * BSTG + n * SRB + c * 16,
                   f2b + s_colidx[ch * 128 + n] + kt * 32 + c * 8);
        cp_commit();
    };

    const int a_row = wmq * 32 + (lane & 15);
    const int a_kh = (lane >> 4) * 8;
    const int b_row = wn * 32 + (lane & 7);
    const int b_kh = ((lane >> 3) & 1) * 8;
    const int gid = lane >> 2, tig = lane & 3;

    for (int ch = 0; ch < NCHUNK; ch++) {
        float acc[2][4][4];
        #pragma unroll
        for (int i = 0; i < 2; i++)
            #pragma unroll
            for (int j = 0; j < 4; j++)
                #pragma unroll
                for (int e = 0; e < 4; e++) acc[i][j][e] = 0.0f;

        issueB(ch, 0, 0);
        issueB(ch, 1, 1);

        #pragma unroll
        for (int kt = 0; kt < 8; kt++) {
            if (kt < 7) cp_wait<1>(); else cp_wait<0>();
            __syncthreads();
            if (kt + 2 < 8) issueB(ch, kt + 2, (kt + 2) % 3);

            const uint32_t sA = Abase + kt * ASEC;
            const uint32_t sB = Bbase + (kt % 3) * BSTG;

            if (mactive) {
                #pragma unroll
                for (int s = 0; s < 2; s++) {
                    uint32_t afr[2][4], bfr[4][2];
                    #pragma unroll
                    for (int mi = 0; mi < 2; mi++)
                        ldsm_x4(afr[mi], sA + (a_row + mi * 16) * SRB + (a_kh + s * 16) * 2);
                    #pragma unroll
                    for (int ni = 0; ni < 4; ni++)
                        ldsm_x2(bfr[ni], sB + (b_row + ni * 8) * SRB + (b_kh + s * 16) * 2);
                    #pragma unroll
                    for (int mi = 0; mi < 2; mi++)
                        #pragma unroll
                        for (int ni = 0; ni < 4; ni++)
                            mma16816(acc[mi][ni], afr[mi], bfr[ni]);
                }
            }
        }

        // epilogue: store this chunk's columns to g_W (layout matches n directly)
        if (mactive) {
            #pragma unroll
            for (int mi = 0; mi < 2; mi++) {
                const int r0 = wmq * 32 + mi * 16 + gid;
                const int r1 = r0 + 8;
                __half* W0 = g_W + (size_t)(start + r0) * WSTRIDE;
                __half* W1 = g_W + (size_t)(start + r1) * WSTRIDE;
                #pragma unroll
                for (int ni = 0; ni < 4; ni++) {
                    const int n = ch * 128 + wn * 32 + ni * 8 + tig * 2;
                    int base, NL;
                    if (n < 290)      { base = 0;   NL = 289; }
                    else if (n < 460) { base = 290; NL = 169; }
                    else if (n < 582) { base = 460; NL = 121; }
                    else              { base = 582; NL = 100; }
                    const bool ok = (n < WSTRIDE) && ((n - base) < NL);
                    if (ok) {
                        if (r0 < rows) *(__half2*)(W0 + n) = __floats2half2_rn(acc[mi][ni][0], acc[mi][ni][1]);
                        if (r1 < rows) *(__half2*)(W1 + n) = __floats2half2_rn(acc[mi][ni][2], acc[mi][ni][3]);
                    }
                }
            }
        }
    }
}

// ===================== combined sampler (all 4 levels) ======================
__global__ void __launch_bounds__(256) corr_sample(const float* __restrict__ cc,
                                                   float* __restrict__ out) {
    const int tid = threadIdx.x, warp = tid >> 5, lane = tid & 31;
    const int p = blockIdx.x * 8 + warp;
    const int b = p >> 12, pix = p & 4095;

    __shared__ float G[8][4][100];
    __shared__ float OB[8][324];

    const float cx = cc[(b * 2 + 0) * HW + pix];
    const float cy = cc[(b * 2 + 1) * HW + pix];
    const int CX = min(7, max(0, ((int)floorf(cx)) >> 3));
    const int CY = min(7, max(0, ((int)floorf(cy)) >> 3));
    const __half* Wp = g_W + (size_t)g_pos[p] * WSTRIDE;

    const int WWl[4]   = {17, 13, 11, 10};
    const int basel[4] = {0, 290, 460, 582};
    const int sizel[4] = {64, 32, 16, 8};
    const int cwl[4]   = {8, 4, 2, 1};

    #pragma unroll
    for (int lvl = 0; lvl < 4; lvl++) {
        const float inv = 1.0f / (float)(1 << lvl);
        const float cxl = cx * inv, cyl = cy * inv;
        const int fxi = (int)floorf(cxl), fyi = (int)floorf(cyl);
        const int dx = fxi - cwl[lvl] * CX;
        const int dy = fyi - cwl[lvl] * CY;
        const int WWc = WWl[lvl], sz = sizel[lvl];
        const __half* base = Wp + basel[lvl];
        #pragma unroll
        for (int c = lane; c < 100; c += 32) {
            const int j = c / 10, i = c - j * 10;
            const int ix = fxi - 4 + i, iy = fyi - 4 + j;
            const bool valid = ((unsigned)ix < (unsigned)sz) && ((unsigned)iy < (unsigned)sz);
            G[warp][lvl][c] = valid ? __half2float(base[(dy + j) * WWc + dx + i]) : 0.0f;
        }
    }
    __syncwarp();

    #pragma unroll
    for (int lvl = 0; lvl < 4; lvl++) {
        const float inv = 1.0f / (float)(1 << lvl);
        const float cxl = cx * inv, cyl = cy * inv;
        const float fx = cxl - floorf(cxl);
        const float fy = cyl - floorf(cyl);
        for (int s = lane; s < 81; s += 32) {
            const int si = s / 9, sj = s - si * 9;
            const float g00 = G[warp][lvl][sj * 10 + si];
            const float g01 = G[warp][lvl][sj * 10 + si + 1];
            const float g10 = G[warp][lvl][(sj + 1) * 10 + si];
            const float g11 = G[warp][lvl][(sj + 1) * 10 + si + 1];
            OB[warp][lvl * 81 + s] = (1.0f - fy) * ((1.0f - fx) * g00 + fx * g01)
                                   + fy * ((1.0f - fx) * g10 + fx * g11);
        }
    }
    __syncthreads();

    const int pix0 = (blockIdx.x * 8) & 4095;
    const int bb = (blockIdx.x * 8) >> 12;
    for (int idx = tid; idx < 324 * 8; idx += 256) {
        const int ch = idx >> 3, pp = idx & 7;
        out[((size_t)bb * 324 + ch) * HW + pix0 + pp] = OB[pp][ch];
    }
}

// ===========================================================================
extern "C" void kernel_launch(void* const* d_in, const int* in_sizes, int n_in,
                              void* d_out, int out_size) {
    const float* fmap1 = (const float*)d_in[0];
    const float* fmap2 = (const float*)d_in[1];
    const float* cc    = (const float*)d_in[2];
    float* out = (float*)d_out;

    static cudaStream_t s1, s2;
    static cudaEvent_t evRoot, evF1, evBin;
    static int inited = 0;
    if (!inited) {
        cudaStreamCreateWithFlags(&s1, cudaStreamNonBlocking);
        cudaStreamCreateWithFlags(&s2, cudaStreamNonBlocking);
        cudaEventCreateWithFlags(&evRoot, cudaEventDisableTiming);
        cudaEventCreateWithFlags(&evF1, cudaEventDisableTiming);
        cudaEventCreateWithFlags(&evBin, cudaEventDisableTiming);
        cudaFuncSetAttribute(fused_gemm, cudaFuncAttributeMaxDynamicSharedMemorySize, GEMM_SMEM);
        inited = 1;
    }

    cudaEventRecord(evRoot, 0);

    // s2: binning
    cudaStreamWaitEvent(s2, evRoot, 0);
    bin_pixels<<<1, 1024, 0, s2>>>(cc);
    cudaEventRecord(evBin, s2);

    // s1: f1 transpose
    cudaStreamWaitEvent(s1, evRoot, 0);
    cvt_f1<<<dim3(HW / 32, CHANNELS / 32, BATCH), dim3(32, 8), 0, s1>>>(fmap1);
    cudaEventRecord(evF1, s1);

    // main: fused f2 convert+transpose+pool
    cvt_pool_f2<<<dim3(64, 4, BATCH), 256>>>(fmap2);

    // main: fused all-level GEMM (needs f2 [main], f1, bin)
    cudaStreamWaitEvent(0, evF1, 0);
    cudaStreamWaitEvent(0, evBin, 0);
    fused_gemm<<<128, 512, GEMM_SMEM>>>();

    // main: combined sampler
    corr_sample<<<(BATCH * HW) / 8, 256>>>(cc, out);
}

// round 12
// speedup vs baseline: 1.5944x; 1.5944x over previous
#include <cuda_runtime.h>
#include <cuda_fp16.h>
#include <cstdint>

#define CHANNELS 256
#define HW 4096
#define BATCH 2
#define F2COLS 5504            // padded pyramid cols per batch (uses 5440)
// level offsets: L0 0 (64x64), L1 4096 (32x32), L2 5120 (16x16), L3 5376 (8x8)
#define WSTRIDE 688            // per-pixel window stride (halves): 290+170+122+106 padded

__device__ __align__(16) __half g_f1h[BATCH * HW * CHANNELS];      // [b][m][k], scaled 1/16
__device__ __align__(16) __half g_f2h[BATCH * F2COLS * CHANNELS];  // [b][col][k]
__device__ __align__(16) __half g_W[(size_t)BATCH * HW * WSTRIDE]; // per-pixel windows (~11 MB)
__device__ int g_binstart[128];
__device__ int g_bincnt[128];
__device__ int g_blist[BATCH * HW];   // sorted pixel ids
__device__ int g_pos[BATCH * HW];     // pixel -> sorted position

// ===================== helpers ========================
__device__ __forceinline__ uint32_t smem_u32(const void* p) {
    uint32_t a;
    asm("{ .reg .u64 t; cvta.to.shared.u64 t, %1; cvt.u32.u64 %0, t; }" : "=r"(a) : "l"(p));
    return a;
}
__device__ __forceinline__ void cp_async16(uint32_t s, const void* g) {
    asm volatile("cp.async.cg.shared.global [%0], [%1], 16;" :: "r"(s), "l"(g));
}
__device__ __forceinline__ void cp_commit() { asm volatile("cp.async.commit_group;"); }
template <int N> __device__ __forceinline__ void cp_wait() {
    asm volatile("cp.async.wait_group %0;" :: "n"(N));
}
__device__ __forceinline__ void ldsm_x4(uint32_t* r, uint32_t addr) {
    asm volatile("ldmatrix.sync.aligned.m8n8.x4.shared.b16 {%0,%1,%2,%3}, [%4];"
                 : "=r"(r[0]), "=r"(r[1]), "=r"(r[2]), "=r"(r[3]) : "r"(addr));
}
__device__ __forceinline__ void ldsm_x2(uint32_t* r, uint32_t addr) {
    asm volatile("ldmatrix.sync.aligned.m8n8.x2.shared.b16 {%0,%1}, [%2];"
                 : "=r"(r[0]), "=r"(r[1]) : "r"(addr));
}
__device__ __forceinline__ void mma16816(float* c, const uint32_t* a, const uint32_t* b) {
    asm volatile("mma.sync.aligned.m16n8k16.row.col.f32.f16.f16.f32 "
                 "{%0,%1,%2,%3}, {%4,%5,%6,%7}, {%8,%9}, {%0,%1,%2,%3};"
                 : "+f"(c[0]), "+f"(c[1]), "+f"(c[2]), "+f"(c[3])
                 : "r"(a[0]), "r"(a[1]), "r"(a[2]), "r"(a[3]), "r"(b[0]), "r"(b[1]));
}

// ======================= f1: transpose + fp16 convert =======================
__global__ void cvt_f1(const float* __restrict__ src) {
    __shared__ float tile[32][33];
    const int b = blockIdx.z, p0 = blockIdx.x * 32, c0 = blockIdx.y * 32;
    const float* s = src + (size_t)b * CHANNELS * HW;
    #pragma unroll
    for (int r = threadIdx.y; r < 32; r += 8)
        tile[r][threadIdx.x] = s[(c0 + r) * HW + p0 + threadIdx.x] * 0.0625f; // 1/sqrt(256)
    __syncthreads();
    __half* d = g_f1h + (size_t)b * HW * CHANNELS;
    #pragma unroll
    for (int r = threadIdx.y; r < 32; r += 8)
        d[(p0 + r) * CHANNELS + c0 + threadIdx.x] = __float2half(tile[threadIdx.x][r]);
}

// ====== f2: fused transpose + fp16 convert + all 3 pool levels ==============
__global__ void __launch_bounds__(256) cvt_pool_f2(const float* __restrict__ src) {
    __shared__ float sfp[64][65];
    __shared__ float sL1[64][17];
    __shared__ float sL2[64][5];
    const int tid = threadIdx.x;
    const int tile = blockIdx.x, cg = blockIdx.y, b = blockIdx.z;
    const int ty = tile >> 3, tx = tile & 7;
    const int c0 = cg * 64;
    const float* s = src + ((size_t)b * CHANNELS + c0) * HW + (ty * 8) * 64 + tx * 8;

    #pragma unroll
    for (int rep = 0; rep < 2; rep++) {
        const int idx = tid + rep * 256;
        const int c = idx >> 3, iy = idx & 7;
        const float4* p = (const float4*)(s + c * HW + iy * 64);
        float4 v0 = p[0], v1 = p[1];
        sfp[c][iy * 8 + 0] = v0.x; sfp[c][iy * 8 + 1] = v0.y;
        sfp[c][iy * 8 + 2] = v0.z; sfp[c][iy * 8 + 3] = v0.w;
        sfp[c][iy * 8 + 4] = v1.x; sfp[c][iy * 8 + 5] = v1.y;
        sfp[c][iy * 8 + 6] = v1.z; sfp[c][iy * 8 + 7] = v1.w;
    }
    __syncthreads();

    __half* f2 = g_f2h + (size_t)b * F2COLS * CHANNELS;

    {   // L0 transpose write
        const int c2 = (tid & 31) * 2;
        #pragma unroll
        for (int pass = 0; pass < 8; pass++) {
            const int pl = (tid >> 5) + pass * 8;
            const int py = ty * 8 + (pl >> 3), px = tx * 8 + (pl & 7);
            *(__half2*)(f2 + (size_t)(py * 64 + px) * CHANNELS + c0 + c2) =
                __floats2half2_rn(sfp[c2][pl], sfp[c2 + 1][pl]);
        }
    }

    #pragma unroll
    for (int rep = 0; rep < 2; rep++) {    // L1: 16 cells
        const int idx = tid + rep * 256;
        const int c = (idx & 31) * 2, cell = idx >> 5;
        const int jy = cell >> 2, jx = cell & 3;
        const int p00 = (2 * jy) * 8 + 2 * jx;
        const float a0 = 0.25f * (sfp[c][p00] + sfp[c][p00 + 1] + sfp[c][p00 + 8] + sfp[c][p00 + 9]);
        const float a1 = 0.25f * (sfp[c + 1][p00] + sfp[c + 1][p00 + 1] + sfp[c + 1][p00 + 8] + sfp[c + 1][p00 + 9]);
        sL1[c][cell] = a0; sL1[c + 1][cell] = a1;
        const int col = 4096 + (ty * 4 + jy) * 32 + tx * 4 + jx;
        *(__half2*)(f2 + (size_t)col * CHANNELS + c0 + c) = __floats2half2_rn(a0, a1);
    }
    __syncthreads();

    if (tid < 128) {                        // L2: 4 cells
        const int c = (tid & 31) * 2, cell = tid >> 5;
        const int Jy = cell >> 1, Jx = cell & 1;
        const int q = (2 * Jy) * 4 + 2 * Jx;
        const float a0 = 0.25f * (sL1[c][q] + sL1[c][q + 1] + sL1[c][q + 4] + sL1[c][q + 5]);
        const float a1 = 0.25f * (sL1[c + 1][q] + sL1[c + 1][q + 1] + sL1[c + 1][q + 4] + sL1[c + 1][q + 5]);
        sL2[c][cell] = a0; sL2[c + 1][cell] = a1;
        const int col = 5120 + (ty * 2 + Jy) * 16 + tx * 2 + Jx;
        *(__half2*)(f2 + (size_t)col * CHANNELS + c0 + c) = __floats2half2_rn(a0, a1);
    }
    __syncthreads();

    if (tid < 32) {                         // L3: 1 cell
        const int c = tid * 2;
        const float a0 = 0.25f * (sL2[c][0] + sL2[c][1] + sL2[c][2] + sL2[c][3]);
        const float a1 = 0.25f * (sL2[c + 1][0] + sL2[c + 1][1] + sL2[c + 1][2] + sL2[c + 1][3]);
        const int col = 5376 + ty * 8 + tx;
        *(__half2*)(f2 + (size_t)col * CHANNELS + c0 + c) = __floats2half2_rn(a0, a1);
    }
}

// ============================ binning =======================================
__global__ void __launch_bounds__(1024) bin_pixels(const float* __restrict__ cc) {
    __shared__ int scnt[128], sstart[128];
    const int tid = threadIdx.x;
    if (tid < 128) scnt[tid] = 0;
    __syncthreads();
    int mycell[8];
    #pragma unroll
    for (int i = 0; i < 8; i++) {
        const int p = tid + i * 1024;
        const int b = p >> 12, pix = p & 4095;
        const float cx = cc[(b * 2 + 0) * HW + pix];
        const float cy = cc[(b * 2 + 1) * HW + pix];
        const int CX = min(7, max(0, ((int)floorf(cx)) >> 3));
        const int CY = min(7, max(0, ((int)floorf(cy)) >> 3));
        mycell[i] = b * 64 + CY * 8 + CX;
        atomicAdd(&scnt[mycell[i]], 1);
    }
    __syncthreads();
    if (tid < 32) {     // warp-parallel exclusive scan, 4 bins/lane
        const int c0 = scnt[tid * 4], c1 = scnt[tid * 4 + 1];
        const int c2 = scnt[tid * 4 + 2], c3 = scnt[tid * 4 + 3];
        const int sum = c0 + c1 + c2 + c3;
        int pre = sum;
        #pragma unroll
        for (int d = 1; d < 32; d <<= 1) {
            const int t = __shfl_up_sync(0xffffffffu, pre, d);
            if (tid >= d) pre += t;
        }
        const int excl = pre - sum;
        sstart[tid * 4] = excl;
        sstart[tid * 4 + 1] = excl + c0;
        sstart[tid * 4 + 2] = excl + c0 + c1;
        sstart[tid * 4 + 3] = excl + c0 + c1 + c2;
        g_binstart[tid * 4] = excl;
        g_binstart[tid * 4 + 1] = excl + c0;
        g_binstart[tid * 4 + 2] = excl + c0 + c1;
        g_binstart[tid * 4 + 3] = excl + c0 + c1 + c2;
        g_bincnt[tid * 4] = c0; g_bincnt[tid * 4 + 1] = c1;
        g_bincnt[tid * 4 + 2] = c2; g_bincnt[tid * 4 + 3] = c3;
    }
    __syncthreads();
    if (tid < 128) scnt[tid] = 0;   // reuse as cursor
    __syncthreads();
    #pragma unroll
    for (int i = 0; i < 8; i++) {
        const int p = tid + i * 1024;
        const int pos = sstart[mycell[i]] + atomicAdd(&scnt[mycell[i]], 1);
        g_blist[pos] = p;
        g_pos[p] = pos;
    }
}

// ============================ binned window GEMM ============================
// One (bin, 64-row chunk, n-split). 8 warps 2(m) x 4(n); warp tile 32 x NW.
#define BK 32
#define SRB 80

template <int WW, int NPC, int WBASE, int LVLOFF, int SIZE, int CELLW>
__global__ void __launch_bounds__(256) binned_gemm() {
    constexpr int NL = WW * WW;
    constexpr int NW = NPC / 4;
    constexpr int NI = NW / 8;
    constexpr int ATILE = 64 * SRB;
    constexpr int BTILE = NPC * SRB;
    constexpr int STAGE = ATILE + BTILE;

    extern __shared__ __align__(16) char smem[];
    __shared__ int s_colidx[NPC];
    __shared__ int s_plist[64];

    const int bin = blockIdx.x, chunk = blockIdx.y;
    const int nbase = blockIdx.z * NPC;
    const int start = g_binstart[bin];
    const int cnt = g_bincnt[bin];
    int rows = cnt - chunk * 64;
    if (rows <= 0) return;
    if (rows > 64) rows = 64;
    const int rows_pad = (rows + 31) & ~31;

    const int tid = threadIdx.x, wid = tid >> 5, lane = tid & 31;
    const int wm = wid & 1, wn = wid >> 1;
    const int b = bin >> 6, cell = bin & 63;
    const int CY = cell >> 3, CX = cell & 7;
    const int wx0 = CELLW * CX - 4, wy0 = CELLW * CY - 4;

    // skip the upper 32-row half entirely if this chunk has <= 32 rows
    const bool mactive = (wm == 0) || (rows > 32);

    for (int n = tid; n < NPC; n += 256) {
        const int ng = nbase + n;
        const int wy = ng / WW, wx = ng - wy * WW;
        const int iy = min(SIZE - 1, max(0, wy0 + wy));
        const int ix = min(SIZE - 1, max(0, wx0 + wx));
        s_colidx[n] = (LVLOFF + iy * SIZE + ix) * CHANNELS;
    }
    if (tid < 64) {
        const int g = start + chunk * 64 + tid;
        s_plist[tid] = g_blist[tid < rows ? g : start];
    }
    __syncthreads();

    const uint32_t sbase = smem_u32(smem);
    const __half* f2b = g_f2h + (size_t)b * F2COLS * CHANNELS;

    auto issue = [&](int kt, int stage) {
        const uint32_t sA = sbase + stage * STAGE;
        const uint32_t sB = sA + ATILE;
        const int kh = kt * BK;
        {   // A: rows_pad x 4 16B-chunks (skip fully-dead rows)
            const int r = tid >> 2, c = tid & 3;
            if (r < rows_pad)
                cp_async16(sA + r * SRB + c * 16,
                           g_f1h + (size_t)s_plist[r] * CHANNELS + kh + c * 8);
        }
        for (int q = tid; q < NPC * 4; q += 256) {
            const int n = q >> 2, c = q & 3;
            cp_async16(sB + n * SRB + c * 16, f2b + s_colidx[n] + kh + c * 8);
        }
        cp_commit();
    };

    float acc[2][NI][4];
    #pragma unroll
    for (int i = 0; i < 2; i++)
        #pragma unroll
        for (int j = 0; j < NI; j++)
            #pragma unroll
            for (int e = 0; e < 4; e++) acc[i][j][e] = 0.0f;

    issue(0, 0);
    issue(1, 1);

    const int a_row = wm * 32 + (lane & 15);
    const int a_kh = (lane >> 4) * 8;
    const int b_row = wn * NW + (lane & 7);
    const int b_kh = ((lane >> 3) & 1) * 8;

    #pragma unroll
    for (int kt = 0; kt < 8; kt++) {
        if (kt < 7) cp_wait<1>(); else cp_wait<0>();
        __syncthreads();
        if (kt + 2 < 8) issue(kt + 2, (kt + 2) % 3);

        const int stage = kt % 3;
        const uint32_t sA = sbase + stage * STAGE;
        const uint32_t sB = sA + ATILE;

        if (mactive) {
            #pragma unroll
            for (int s = 0; s < 2; s++) {
                uint32_t afr[2][4], bfr[NI][2];
                #pragma unroll
                for (int mi = 0; mi < 2; mi++)
                    ldsm_x4(afr[mi], sA + (a_row + mi * 16) * SRB + (a_kh + s * 16) * 2);
                #pragma unroll
                for (int ni = 0; ni < NI; ni++)
                    ldsm_x2(bfr[ni], sB + (b_row + ni * 8) * SRB + (b_kh + s * 16) * 2);
                #pragma unroll
                for (int mi = 0; mi < 2; mi++)
                    #pragma unroll
                    for (int ni = 0; ni < NI; ni++)
                        mma16816(acc[mi][ni], afr[mi], bfr[ni]);
            }
        }
    }

    const int gid = lane >> 2, tig = lane & 3;
    #pragma unroll
    for (int mi = 0; mi < 2; mi++) {
        const int r0 = wm * 32 + mi * 16 + gid;
        const int r1 = r0 + 8;
        __half* W0 = g_W + (size_t)(start + chunk * 64 + r0) * WSTRIDE + WBASE;
        __half* W1 = g_W + (size_t)(start + chunk * 64 + r1) * WSTRIDE + WBASE;
        #pragma unroll
        for (int ni = 0; ni < NI; ni++) {
            const int cbg = nbase + wn * NW + ni * 8 + tig * 2;
            if (cbg + 1 < NL) {
                if (r0 < rows) *(__half2*)(W0 + cbg) = __floats2half2_rn(acc[mi][ni][0], acc[mi][ni][1]);
                if (r1 < rows) *(__half2*)(W1 + cbg) = __floats2half2_rn(acc[mi][ni][2], acc[mi][ni][3]);
            } else if (cbg < NL) {
                if (r0 < rows) W0[cbg] = __float2half(acc[mi][ni][0]);
                if (r1 < rows) W1[cbg] = __float2half(acc[mi][ni][2]);
            }
        }
    }
}

// ======================== per-level sampler =================================
template <int LVL, int WW, int WBASE, int SIZE, int CELLW>
__global__ void __launch_bounds__(256) sample_level(const float* __restrict__ cc,
                                                    float* __restrict__ out) {
    const int tid = threadIdx.x, warp = tid >> 5, lane = tid & 31;
    const int p = blockIdx.x * 8 + warp;
    const int b = p >> 12, pix = p & 4095;

    __shared__ float G[8][100];
    __shared__ float OB[8][81];

    const float cx = cc[(b * 2 + 0) * HW + pix];
    const float cy = cc[(b * 2 + 1) * HW + pix];
    const int CX = min(7, max(0, ((int)floorf(cx)) >> 3));
    const int CY = min(7, max(0, ((int)floorf(cy)) >> 3));
    const __half* base = g_W + (size_t)g_pos[p] * WSTRIDE + WBASE;

    const float inv = 1.0f / (float)(1 << LVL);
    const float cxl = cx * inv, cyl = cy * inv;
    const int fxi = (int)floorf(cxl), fyi = (int)floorf(cyl);
    const int dx = fxi - CELLW * CX;
    const int dy = fyi - CELLW * CY;

    #pragma unroll
    for (int c = lane; c < 100; c += 32) {
        const int j = c / 10, i = c - j * 10;
        const int ix = fxi - 4 + i, iy = fyi - 4 + j;
        const bool valid = ((unsigned)ix < (unsigned)SIZE) && ((unsigned)iy < (unsigned)SIZE);
        G[warp][c] = valid ? __half2float(base[(dy + j) * WW + dx + i]) : 0.0f;
    }
    __syncwarp();

    const float fx = cxl - floorf(cxl);
    const float fy = cyl - floorf(cyl);
    for (int s = lane; s < 81; s += 32) {
        const int si = s / 9, sj = s - si * 9;
        const float g00 = G[warp][sj * 10 + si];
        const float g01 = G[warp][sj * 10 + si + 1];
        const float g10 = G[warp][(sj + 1) * 10 + si];
        const float g11 = G[warp][(sj + 1) * 10 + si + 1];
        OB[warp][s] = (1.0f - fy) * ((1.0f - fx) * g00 + fx * g01)
                    + fy * ((1.0f - fx) * g10 + fx * g11);
    }
    __syncthreads();

    const int pix0 = (blockIdx.x * 8) & 4095;
    const int bb = (blockIdx.x * 8) >> 12;
    for (int idx = tid; idx < 81 * 8; idx += 256) {
        const int ch = idx >> 3, pp = idx & 7;
        out[((size_t)bb * 324 + LVL * 81 + ch) * HW + pix0 + pp] = OB[pp][ch];
    }
}

// ===========================================================================
#define SMEM_L0 (3 * ((64 + 160) * SRB))   // 53760
#define SMEM_L1 (3 * ((64 + 192) * SRB))   // 61440
#define SMEM_L2 (3 * ((64 + 128) * SRB))   // 46080

extern "C" void kernel_launch(void* const* d_in, const int* in_sizes, int n_in,
                              void* d_out, int out_size) {
    const float* fmap1 = (const float*)d_in[0];
    const float* fmap2 = (const float*)d_in[1];
    const float* cc    = (const float*)d_in[2];
    float* out = (float*)d_out;

    static cudaStream_t s1, s2, s3;
    static cudaEvent_t evRoot, evF1, evBin, evF2, evE1, evE2, evE3;
    static int inited = 0;
    if (!inited) {
        cudaStreamCreateWithFlags(&s1, cudaStreamNonBlocking);
        cudaStreamCreateWithFlags(&s2, cudaStreamNonBlocking);
        cudaStreamCreateWithFlags(&s3, cudaStreamNonBlocking);
        cudaEventCreateWithFlags(&evRoot, cudaEventDisableTiming);
        cudaEventCreateWithFlags(&evF1, cudaEventDisableTiming);
        cudaEventCreateWithFlags(&evBin, cudaEventDisableTiming);
        cudaEventCreateWithFlags(&evF2, cudaEventDisableTiming);
        cudaEventCreateWithFlags(&evE1, cudaEventDisableTiming);
        cudaEventCreateWithFlags(&evE2, cudaEventDisableTiming);
        cudaEventCreateWithFlags(&evE3, cudaEventDisableTiming);
        cudaFuncSetAttribute(binned_gemm<17, 160, 0, 0, 64, 8>,
                             cudaFuncAttributeMaxDynamicSharedMemorySize, SMEM_L0);
        cudaFuncSetAttribute(binned_gemm<13, 192, 290, 4096, 32, 4>,
                             cudaFuncAttributeMaxDynamicSharedMemorySize, SMEM_L1);
        cudaFuncSetAttribute(binned_gemm<11, 128, 460, 5120, 16, 2>,
                             cudaFuncAttributeMaxDynamicSharedMemorySize, SMEM_L2);
        cudaFuncSetAttribute(binned_gemm<10, 128, 582, 5376, 8, 1>,
                             cudaFuncAttributeMaxDynamicSharedMemorySize, SMEM_L2);
        inited = 1;
    }

    cudaEventRecord(evRoot, 0);

    // s2: binning
    cudaStreamWaitEvent(s2, evRoot, 0);
    bin_pixels<<<1, 1024, 0, s2>>>(cc);
    cudaEventRecord(evBin, s2);

    // s1: f1 transpose
    cudaStreamWaitEvent(s1, evRoot, 0);
    cvt_f1<<<dim3(HW / 32, CHANNELS / 32, BATCH), dim3(32, 8), 0, s1>>>(fmap1);
    cudaEventRecord(evF1, s1);

    // main: fused f2 convert+transpose+pool (all levels ready after this)
    cvt_pool_f2<<<dim3(64, 4, BATCH), 256>>>(fmap2);
    cudaEventRecord(evF2, 0);

    // s3: level 0 (N split 2) -> sampler 0
    cudaStreamWaitEvent(s3, evF2, 0);
    cudaStreamWaitEvent(s3, evF1, 0);
    cudaStreamWaitEvent(s3, evBin, 0);
    binned_gemm<17, 160, 0, 0, 64, 8><<<dim3(128, 2, 2), 256, SMEM_L0, s3>>>();
    sample_level<0, 17, 0, 64, 8><<<1024, 256, 0, s3>>>(cc, out);
    cudaEventRecord(evE3, s3);

    // s1: level 1 -> sampler 1
    cudaStreamWaitEvent(s1, evF2, 0);
    cudaStreamWaitEvent(s1, evBin, 0);
    binned_gemm<13, 192, 290, 4096, 32, 4><<<dim3(128, 2, 1), 256, SMEM_L1, s1>>>();
    sample_level<1, 13, 290, 32, 4><<<1024, 256, 0, s1>>>(cc, out);
    cudaEventRecord(evE1, s1);

    // s2: level 2 -> sampler 2
    cudaStreamWaitEvent(s2, evF2, 0);
    cudaStreamWaitEvent(s2, evF1, 0);
    binned_gemm<11, 128, 460, 5120, 16, 2><<<dim3(128, 2, 1), 256, SMEM_L2, s2>>>();
    sample_level<2, 11, 460, 16, 2><<<1024, 256, 0, s2>>>(cc, out);
    cudaEventRecord(evE2, s2);

    // main: level 3 -> sampler 3
    cudaStreamWaitEvent(0, evF1, 0);
    cudaStreamWaitEvent(0, evBin, 0);
    binned_gemm<10, 128, 582, 5376, 8, 1><<<dim3(128, 2, 1), 256, SMEM_L2>>>();
    sample_level<3, 10, 582, 8, 1><<<1024, 256>>>(cc, out);

    // join
    cudaStreamWaitEvent(0, evE1, 0);
    cudaStreamWaitEvent(0, evE2, 0);
    cudaStreamWaitEvent(0, evE3, 0);
}